// round 2
// baseline (speedup 1.0000x reference)
#include <cuda_runtime.h>
#include <math.h>
#include <stdint.h>

// Problem constants (fixed shapes from reference)
#define Bv 8
#define Tv 1024
#define Cv 1024
#define Hv 16
#define DHv 64
#define Fv 4096
#define BT (Bv*Tv)          // 8192
#define QKVN (3*Cv)         // 3072

// ---------------- scratch (device globals: allocation-free) ----------------
__device__ float g_x1[BT*Cv];        // ln1(x)
__device__ float g_qkv[BT*QKVN];     // packed q|k|v rows
__device__ float g_Wqkv[Cv*QKVN];    // packed weight [K=C rows][N=3C cols]
__device__ float g_bqkv[QKVN];
__device__ float g_M[Bv*Hv*DHv*DHv]; // (K^T V)/32 per (b,h)
__device__ float g_cat[BT*Cv];       // concatenated heads
__device__ float g_y[BT*Cv];         // x1 + attn
__device__ float g_x2[BT*Cv];        // ln2(y)
__device__ float g_h[BT*Fv];         // gelu(x2 W1 + b1)

// ---------------- LayerNorm: one block per row of 1024 ----------------
__global__ void ln_kernel(const float* __restrict__ x, const float* __restrict__ w,
                          const float* __restrict__ bb, float* __restrict__ y)
{
    int row = blockIdx.x;
    int t = threadIdx.x;  // 256 threads, float4 each
    const float4* xr = (const float4*)(x + (size_t)row * Cv);
    float4 v = xr[t];
    float s  = v.x + v.y + v.z + v.w;
    float ss = v.x*v.x + v.y*v.y + v.z*v.z + v.w*v.w;
    #pragma unroll
    for (int o = 16; o > 0; o >>= 1) {
        s  += __shfl_xor_sync(0xffffffffu, s,  o);
        ss += __shfl_xor_sync(0xffffffffu, ss, o);
    }
    __shared__ float shs[8], shss[8], par[2];
    if ((t & 31) == 0) { shs[t >> 5] = s; shss[t >> 5] = ss; }
    __syncthreads();
    if (t == 0) {
        float S = 0.f, SS = 0.f;
        #pragma unroll
        for (int i = 0; i < 8; i++) { S += shs[i]; SS += shss[i]; }
        float mu  = S * (1.0f / 1024.0f);
        float var = SS * (1.0f / 1024.0f) - mu * mu;
        par[0] = mu;
        par[1] = rsqrtf(var + 1e-3f);
    }
    __syncthreads();
    float mu = par[0], rs = par[1];
    float4 wv = ((const float4*)w)[t];
    float4 bv = ((const float4*)bb)[t];
    float4 o;
    o.x = (v.x - mu) * rs * wv.x + bv.x;
    o.y = (v.y - mu) * rs * wv.y + bv.y;
    o.z = (v.z - mu) * rs * wv.z + bv.z;
    o.w = (v.w - mu) * rs * wv.w + bv.w;
    ((float4*)(y + (size_t)row * Cv))[t] = o;
}

// -------- pack Wq/Wk/Wv [H,C,Dh] -> [C, 3C] row-major + packed bias --------
__global__ void pack_kernel(const float* __restrict__ Wq, const float* __restrict__ Wk,
                            const float* __restrict__ Wv,
                            const float* __restrict__ bq, const float* __restrict__ bk,
                            const float* __restrict__ bv,
                            float* __restrict__ Wo, float* __restrict__ bo)
{
    int idx = blockIdx.x * 256 + threadIdx.x;       // over C*3C
    if (idx >= Cv * QKVN) return;
    int c = idx / QKVN, col = idx % QKVN;
    int sel = col >> 10;                             // 0=q,1=k,2=v
    int n = col & 1023;
    int h = n >> 6, d = n & 63;
    const float* W = (sel == 0) ? Wq : (sel == 1) ? Wk : Wv;
    Wo[idx] = W[((size_t)h * Cv + c) * DHv + d];
    if (c == 0) {
        const float* B = (sel == 0) ? bq : (sel == 1) ? bk : bv;
        bo[col] = B[h * DHv + d];
    }
}

// ---------------- SGEMM: C[M,N] = A[M,K] * B[K,N] + epilogue ----------------
// 128x128 tile, 256 threads, 8x8 per thread, K-slab = 16.
// EPI: 0 = +bias ; 1 = +bias + res ; 2 = gelu(+bias)
template<int EPI>
__global__ __launch_bounds__(256, 2)
void gemm128(const float* __restrict__ A, const float* __restrict__ Bm,
             const float* __restrict__ bias, const float* __restrict__ res,
             float* __restrict__ C, int M, int N, int K)
{
    __shared__ float As[16][132];   // padded, stored transposed (As[k][m])
    __shared__ float Bs[16][128];
    int tid = threadIdx.x;
    int m0 = blockIdx.y * 128, n0 = blockIdx.x * 128;
    int tm = tid >> 4, tn = tid & 15;

    float acc[8][8];
    #pragma unroll
    for (int i = 0; i < 8; i++)
        #pragma unroll
        for (int j = 0; j < 8; j++) acc[i][j] = 0.f;

    for (int k0 = 0; k0 < K; k0 += 16) {
        // A tile: 128 rows x 16 cols = 512 float4, transposed into As
        #pragma unroll
        for (int u = 0; u < 2; u++) {
            int idx = tid + 256 * u;
            int r = idx >> 2, c4 = idx & 3;
            float4 v = *(const float4*)(A + (size_t)(m0 + r) * K + k0 + c4 * 4);
            As[c4*4+0][r] = v.x; As[c4*4+1][r] = v.y;
            As[c4*4+2][r] = v.z; As[c4*4+3][r] = v.w;
        }
        // B tile: 16 rows x 128 cols, direct copy
        #pragma unroll
        for (int u = 0; u < 2; u++) {
            int idx = tid + 256 * u;
            int kk = idx >> 5, x4 = idx & 31;
            *(float4*)&Bs[kk][x4*4] =
                *(const float4*)(Bm + (size_t)(k0 + kk) * N + n0 + x4 * 4);
        }
        __syncthreads();
        #pragma unroll
        for (int kk = 0; kk < 16; kk++) {
            float a[8], b[8];
            #pragma unroll
            for (int i = 0; i < 8; i++) a[i] = As[kk][tm * 8 + i];
            #pragma unroll
            for (int j = 0; j < 8; j++) b[j] = Bs[kk][tn * 8 + j];
            #pragma unroll
            for (int i = 0; i < 8; i++)
                #pragma unroll
                for (int j = 0; j < 8; j++)
                    acc[i][j] += a[i] * b[j];
        }
        __syncthreads();
    }

    #pragma unroll
    for (int i = 0; i < 8; i++) {
        int m = m0 + tm * 8 + i;
        #pragma unroll
        for (int j = 0; j < 8; j++) {
            int n = n0 + tn * 8 + j;
            float v = acc[i][j] + bias[n];
            if (EPI == 1) v += res[(size_t)m * N + n];
            if (EPI == 2) v = 0.5f * v * (1.0f + erff(v * 0.70710678118654752f));
            C[(size_t)m * N + n] = v;
        }
    }
}

// --------- attention collapsed: M = (K^T V) * C^-0.5 per (b,h) ---------
__global__ void ktv_kernel(const float* __restrict__ qkv, float* __restrict__ Mb)
{
    int bh = blockIdx.x;               // 128 blocks
    int b = bh >> 4, h = bh & 15;
    __shared__ float Ks[32][64], Vs[32][64];
    int tid = threadIdx.x;
    int ty = tid >> 4, tx = tid & 15;  // 16x16 threads, 4x4 outputs each
    float acc[4][4];
    #pragma unroll
    for (int i = 0; i < 4; i++)
        #pragma unroll
        for (int j = 0; j < 4; j++) acc[i][j] = 0.f;

    const float* baseK = qkv + (size_t)b * Tv * QKVN + 1024 + h * 64;
    const float* baseV = baseK + 1024;

    for (int t0 = 0; t0 < Tv; t0 += 32) {
        #pragma unroll
        for (int u = 0; u < 2; u++) {
            int idx = tid + 256 * u;       // 0..511
            int r = idx >> 4, c4 = idx & 15;
            *(float4*)&Ks[r][c4*4] = *(const float4*)(baseK + (size_t)(t0 + r) * QKVN + c4 * 4);
            *(float4*)&Vs[r][c4*4] = *(const float4*)(baseV + (size_t)(t0 + r) * QKVN + c4 * 4);
        }
        __syncthreads();
        #pragma unroll
        for (int tt = 0; tt < 32; tt++) {
            float a[4], v[4];
            #pragma unroll
            for (int i = 0; i < 4; i++) a[i] = Ks[tt][ty * 4 + i];
            #pragma unroll
            for (int j = 0; j < 4; j++) v[j] = Vs[tt][tx * 4 + j];
            #pragma unroll
            for (int i = 0; i < 4; i++)
                #pragma unroll
                for (int j = 0; j < 4; j++)
                    acc[i][j] += a[i] * v[j];
        }
        __syncthreads();
    }
    float* out = Mb + (size_t)bh * 4096;
    #pragma unroll
    for (int i = 0; i < 4; i++)
        #pragma unroll
        for (int j = 0; j < 4; j++)
            out[(ty * 4 + i) * 64 + tx * 4 + j] = acc[i][j] * 0.03125f;  // 1/sqrt(1024)
}

// --------- heads = Q @ M, written straight into concat layout ---------
__global__ void qm_kernel(const float* __restrict__ qkv, const float* __restrict__ Mb,
                          float* __restrict__ cat)
{
    int bh = blockIdx.y;               // 128
    int b = bh >> 4, h = bh & 15;
    int t0 = blockIdx.x * 128;         // 8 tiles of T
    __shared__ float Ms[64][64];       // 16 KB
    __shared__ float Qs[128][64];      // 32 KB
    int tid = threadIdx.x;

    const float* Mp = Mb + (size_t)bh * 4096;
    #pragma unroll
    for (int u = 0; u < 4; u++)
        ((float4*)Ms)[tid + 256 * u] = ((const float4*)Mp)[tid + 256 * u];

    const float* baseQ = qkv + (size_t)b * Tv * QKVN + h * 64;
    #pragma unroll
    for (int u = 0; u < 8; u++) {
        int idx = tid + 256 * u;       // 0..2047
        int r = idx >> 4, c4 = idx & 15;
        *(float4*)&Qs[r][c4*4] = *(const float4*)(baseQ + (size_t)(t0 + r) * QKVN + c4 * 4);
    }
    __syncthreads();

    int j = tid & 63, rb = tid >> 6;   // 4 row streams
    float* outbase = cat + (size_t)(b * Tv + t0) * Cv + h * 64 + j;
    #pragma unroll
    for (int rr = 0; rr < 32; rr++) {
        int row = rb * 32 + rr;
        float acc = 0.f;
        #pragma unroll
        for (int i = 0; i < 64; i++) acc += Qs[row][i] * Ms[i][j];
        outbase[(size_t)row * Cv] = acc;
    }
}

// ---------------- launch ----------------
extern "C" void kernel_launch(void* const* d_in, const int* in_sizes, int n_in,
                              void* d_out, int out_size)
{
    (void)in_sizes; (void)n_in; (void)out_size;
    const float* x    = (const float*)d_in[0];
    const float* Wq   = (const float*)d_in[1];
    const float* bq   = (const float*)d_in[2];
    const float* Wk   = (const float*)d_in[3];
    const float* bk   = (const float*)d_in[4];
    const float* Wv   = (const float*)d_in[5];
    const float* bv   = (const float*)d_in[6];
    const float* Wp   = (const float*)d_in[7];
    const float* bp   = (const float*)d_in[8];
    const float* W1   = (const float*)d_in[9];
    const float* b1   = (const float*)d_in[10];
    const float* W2   = (const float*)d_in[11];
    const float* b2   = (const float*)d_in[12];
    const float* ln1w = (const float*)d_in[13];
    const float* ln1b = (const float*)d_in[14];
    const float* ln2w = (const float*)d_in[15];
    const float* ln2b = (const float*)d_in[16];
    float* out = (float*)d_out;

    float *px1, *pqkv, *pWqkv, *pbqkv, *pM, *pcat, *py, *px2, *ph;
    cudaGetSymbolAddress((void**)&px1,   g_x1);
    cudaGetSymbolAddress((void**)&pqkv,  g_qkv);
    cudaGetSymbolAddress((void**)&pWqkv, g_Wqkv);
    cudaGetSymbolAddress((void**)&pbqkv, g_bqkv);
    cudaGetSymbolAddress((void**)&pM,    g_M);
    cudaGetSymbolAddress((void**)&pcat,  g_cat);
    cudaGetSymbolAddress((void**)&py,    g_y);
    cudaGetSymbolAddress((void**)&px2,   g_x2);
    cudaGetSymbolAddress((void**)&ph,    g_h);

    // 1. pack QKV weights/biases into one GEMM operand
    pack_kernel<<<(Cv * QKVN + 255) / 256, 256>>>(Wq, Wk, Wv, bq, bk, bv, pWqkv, pbqkv);
    // 2. x1 = LN1(x)
    ln_kernel<<<BT, 256>>>(x, ln1w, ln1b, px1);
    // 3. qkv = x1 @ Wqkv + bqkv          [8192,1024]x[1024,3072]
    gemm128<0><<<dim3(QKVN / 128, BT / 128), 256>>>(px1, pWqkv, pbqkv, nullptr, pqkv,
                                                    BT, QKVN, Cv);
    // 4. M = (K^T V)/32 per (b,h)        -- attention collapsed via associativity
    ktv_kernel<<<Bv * Hv, 256>>>(pqkv, pM);
    // 5. cat = Q @ M                      (concatenated heads)
    qm_kernel<<<dim3(Tv / 128, Bv * Hv), 256>>>(pqkv, pM, pcat);
    // 6. y = x1 + cat @ Wp + bp
    gemm128<1><<<dim3(Cv / 128, BT / 128), 256>>>(pcat, Wp, bp, px1, py, BT, Cv, Cv);
    // 7. x2 = LN2(y)
    ln_kernel<<<BT, 256>>>(py, ln2w, ln2b, px2);
    // 8. h = gelu(x2 @ W1 + b1)          [8192,1024]x[1024,4096]
    gemm128<2><<<dim3(Fv / 128, BT / 128), 256>>>(px2, W1, b1, nullptr, ph, BT, Fv, Cv);
    // 9. out = x2 + h @ W2 + b2          [8192,4096]x[4096,1024]
    gemm128<1><<<dim3(Cv / 128, BT / 128), 256>>>(ph, W2, b2, px2, out, BT, Cv, Fv);
}

// round 4
// speedup vs baseline: 1.8807x; 1.8807x over previous
#include <cuda_runtime.h>
#include <math.h>
#include <stdint.h>

// Problem constants
#define Bv 8
#define Tv 1024
#define Cv 1024
#define Hv 16
#define DHv 64
#define Fv 4096
#define BT (Bv*Tv)          // 8192
#define QKVN (3*Cv)         // 3072

// ---------------- scratch ----------------
__device__ float g_x1[BT*Cv];
__device__ float g_qkv[BT*QKVN];
__device__ float g_Wqkv[QKVN*Cv];    // [N=3C, K=C] row-major (K-major operand)
__device__ float g_bqkv[QKVN];
__device__ float g_M[Bv*Hv*DHv*DHv];
__device__ float g_cat[BT*Cv];
__device__ float g_y[BT*Cv];
__device__ float g_x2[BT*Cv];
__device__ float g_h[BT*Fv];
__device__ float g_WpT[Cv*Cv];       // [N=C, K=C]
__device__ float g_W1T[Fv*Cv];       // [N=F, K=C]
__device__ float g_W2T[Cv*Fv];       // [N=C, K=F]

// ---------------- helpers ----------------
__device__ __forceinline__ uint32_t smem_u32(const void* p) {
    uint32_t a;
    asm("{ .reg .u64 t; cvta.to.shared.u64 t, %1; cvt.u32.u64 %0, t; }" : "=r"(a) : "l"(p));
    return a;
}
__device__ __forceinline__ float tf32r(float x) {
    uint32_t u; asm("cvt.rn.tf32.f32 %0, %1;" : "=r"(u) : "f"(x));
    return __uint_as_float(u);
}
__device__ __forceinline__ void cp_async16(uint32_t dst, const void* src) {
    asm volatile("cp.async.cg.shared.global [%0], [%1], 16;" :: "r"(dst), "l"(src) : "memory");
}
__device__ __forceinline__ void cp_commit() { asm volatile("cp.async.commit_group;" ::: "memory"); }
template<int N> __device__ __forceinline__ void cp_wait() {
    asm volatile("cp.async.wait_group %0;" :: "n"(N) : "memory");
}

__device__ __forceinline__ void mma_tf32(float* d, const uint32_t* a, const uint32_t* b) {
    asm volatile(
        "mma.sync.aligned.m16n8k8.row.col.f32.tf32.tf32.f32 "
        "{%0,%1,%2,%3}, {%4,%5,%6,%7}, {%8,%9}, {%0,%1,%2,%3};"
        : "+f"(d[0]), "+f"(d[1]), "+f"(d[2]), "+f"(d[3])
        : "r"(a[0]), "r"(a[1]), "r"(a[2]), "r"(a[3]), "r"(b[0]), "r"(b[1]));
}

__device__ __forceinline__ float gelu_f(float v) {
    return 0.5f * v * (1.0f + erff(v * 0.70710678118654752f));
}

// ---------------- tf32 mma.sync GEMM: C[M,N] = A[M,K] * B^T (B given [N,K]) ----------------
// 128x128 CTA tile, 256 threads (8 warps, 4(M) x 2(N)), warp tile 32x64, BK=16,
// 3-stage cp.async pipeline. SMEM tiles [128][20] floats (conflict-free frag reads).
// EPI: 0 = +bias ; 1 = +bias+res ; 2 = tf32(gelu(+bias))
#define NSTAGE 3
#define ROWF   20                      // floats per smem row (16 data + 4 pad)
#define TILEF  (128*ROWF)              // 2560 floats
#define TILEB  (TILEF*4)               // 10240 bytes
#define STAGEB (2*TILEB)               // 20480 bytes

template<int EPI>
__global__ __launch_bounds__(256, 2)
void mm_gemm(const float* __restrict__ A, const float* __restrict__ B,
             const float* __restrict__ bias, const float* __restrict__ res,
             float* __restrict__ C, int M, int N, int K)
{
    extern __shared__ float sm[];
    const int tid = threadIdx.x, wid = tid >> 5, lane = tid & 31;
    const int m0 = blockIdx.y * 128, n0 = blockIdx.x * 128;
    const int wm = wid & 3, wn = wid >> 2;        // warp grid 4x2
    const uint32_t sbase = smem_u32(sm);

    // ---- per-thread cp.async slots: 2 A-chunks + 2 B-chunks (16B each) ----
    const float* aSrc[2]; uint32_t adst[2];
    const float* bSrc[2]; uint32_t bdst[2];
    #pragma unroll
    for (int u = 0; u < 2; u++) {
        int idx = u * 256 + tid;          // 0..511
        int row = idx >> 2, c = idx & 3;  // row 0..127, 16B chunk 0..3
        aSrc[u] = A + (size_t)(m0 + row) * K + c * 4;
        bSrc[u] = B + (size_t)(n0 + row) * K + c * 4;
        adst[u] = row * (ROWF * 4) + c * 16;
        bdst[u] = TILEB + adst[u];
    }

    #define ISSUE_STAGE(st, it) do {                                          \
        uint32_t _sb = sbase + (st) * STAGEB;                                 \
        _Pragma("unroll") for (int _u = 0; _u < 2; _u++)                      \
            cp_async16(_sb + adst[_u], aSrc[_u] + (size_t)(it) * 16);         \
        _Pragma("unroll") for (int _u = 0; _u < 2; _u++)                      \
            cp_async16(_sb + bdst[_u], bSrc[_u] + (size_t)(it) * 16);         \
        cp_commit(); } while (0)

    // ---- fragment smem offsets (floats) ----
    int aoff[2], boff[8];
    #pragma unroll
    for (int mi = 0; mi < 2; mi++)
        aoff[mi] = (wm * 32 + mi * 16 + (lane >> 2)) * ROWF + (lane & 3);
    #pragma unroll
    for (int nj = 0; nj < 8; nj++)
        boff[nj] = (wn * 64 + nj * 8 + (lane >> 2)) * ROWF + (lane & 3);

    float acc[2][8][4];
    #pragma unroll
    for (int mi = 0; mi < 2; mi++)
        #pragma unroll
        for (int nj = 0; nj < 8; nj++)
            #pragma unroll
            for (int q = 0; q < 4; q++) acc[mi][nj][q] = 0.f;

    const int NIT = K >> 4;               // BK = 16
    #pragma unroll
    for (int p = 0; p < NSTAGE - 1; p++) ISSUE_STAGE(p, p);

    for (int it = 0; it < NIT; it++) {
        if (it + 1 == NIT) cp_wait<0>(); else cp_wait<NSTAGE - 2>();
        __syncthreads();
        int nit = it + NSTAGE - 1;
        if (nit < NIT) ISSUE_STAGE(nit % NSTAGE, nit);

        const float* sA = sm + (it % NSTAGE) * (STAGEB / 4);
        const float* sB = sA + TILEF;
        #pragma unroll
        for (int kk = 0; kk < 2; kk++) {
            uint32_t af[2][4], bf[8][2];
            #pragma unroll
            for (int mi = 0; mi < 2; mi++) {
                int o = aoff[mi] + kk * 8;
                af[mi][0] = __float_as_uint(sA[o]);
                af[mi][1] = __float_as_uint(sA[o + 8 * ROWF]);
                af[mi][2] = __float_as_uint(sA[o + 4]);
                af[mi][3] = __float_as_uint(sA[o + 8 * ROWF + 4]);
            }
            #pragma unroll
            for (int nj = 0; nj < 8; nj++) {
                int o = boff[nj] + kk * 8;
                bf[nj][0] = __float_as_uint(sB[o]);
                bf[nj][1] = __float_as_uint(sB[o + 4]);
            }
            #pragma unroll
            for (int mi = 0; mi < 2; mi++)
                #pragma unroll
                for (int nj = 0; nj < 8; nj++)
                    mma_tf32(acc[mi][nj], af[mi], bf[nj]);
        }
    }

    // ---- epilogue ----
    #pragma unroll
    for (int mi = 0; mi < 2; mi++) {
        int r0 = m0 + wm * 32 + mi * 16 + (lane >> 2);
        #pragma unroll
        for (int nj = 0; nj < 8; nj++) {
            int cb = n0 + wn * 64 + nj * 8 + (lane & 3) * 2;
            float2 bv = *(const float2*)(bias + cb);
            #pragma unroll
            for (int half = 0; half < 2; half++) {
                int r = r0 + half * 8;
                float vx = acc[mi][nj][half * 2 + 0] + bv.x;
                float vy = acc[mi][nj][half * 2 + 1] + bv.y;
                if (EPI == 1) {
                    float2 rv = *(const float2*)(res + (size_t)r * N + cb);
                    vx += rv.x; vy += rv.y;
                }
                if (EPI == 2) { vx = tf32r(gelu_f(vx)); vy = tf32r(gelu_f(vy)); }
                *(float2*)(C + (size_t)r * N + cb) = make_float2(vx, vy);
            }
        }
    }
    #undef ISSUE_STAGE
}

// ---------------- LayerNorm (tf32-rounded output) ----------------
__global__ void ln_kernel(const float* __restrict__ x, const float* __restrict__ w,
                          const float* __restrict__ bb, float* __restrict__ y)
{
    int row = blockIdx.x;
    int t = threadIdx.x;
    const float4* xr = (const float4*)(x + (size_t)row * Cv);
    float4 v = xr[t];
    float s  = v.x + v.y + v.z + v.w;
    float ss = v.x*v.x + v.y*v.y + v.z*v.z + v.w*v.w;
    #pragma unroll
    for (int o = 16; o > 0; o >>= 1) {
        s  += __shfl_xor_sync(0xffffffffu, s,  o);
        ss += __shfl_xor_sync(0xffffffffu, ss, o);
    }
    __shared__ float shs[8], shss[8], par[2];
    if ((t & 31) == 0) { shs[t >> 5] = s; shss[t >> 5] = ss; }
    __syncthreads();
    if (t == 0) {
        float S = 0.f, SS = 0.f;
        #pragma unroll
        for (int i = 0; i < 8; i++) { S += shs[i]; SS += shss[i]; }
        float mu  = S * (1.0f / 1024.0f);
        float var = SS * (1.0f / 1024.0f) - mu * mu;
        par[0] = mu; par[1] = rsqrtf(var + 1e-3f);
    }
    __syncthreads();
    float mu = par[0], rs = par[1];
    float4 wv = ((const float4*)w)[t];
    float4 bv = ((const float4*)bb)[t];
    float4 o;
    o.x = tf32r((v.x - mu) * rs * wv.x + bv.x);
    o.y = tf32r((v.y - mu) * rs * wv.y + bv.y);
    o.z = tf32r((v.z - mu) * rs * wv.z + bv.z);
    o.w = tf32r((v.w - mu) * rs * wv.w + bv.w);
    ((float4*)(y + (size_t)row * Cv))[t] = o;
}

// -------- pack Wq/Wk/Wv [H,C,Dh] -> [N=3C, K=C] (tf32) + bias --------
__global__ void pack_kernel(const float* __restrict__ Wq, const float* __restrict__ Wk,
                            const float* __restrict__ Wv,
                            const float* __restrict__ bq, const float* __restrict__ bk,
                            const float* __restrict__ bv,
                            float* __restrict__ Wo, float* __restrict__ bo)
{
    int idx = blockIdx.x * 256 + threadIdx.x;       // over 3C*C
    if (idx >= QKVN * Cv) return;
    int n = idx / Cv, k = idx % Cv;
    int sel = n >> 10;
    int hh = (n & 1023) >> 6, d = n & 63;
    const float* W = (sel == 0) ? Wq : (sel == 1) ? Wk : Wv;
    Wo[idx] = tf32r(W[((size_t)hh * Cv + k) * DHv + d]);
    if (k == 0) {
        const float* B = (sel == 0) ? bq : (sel == 1) ? bk : bv;
        bo[n] = B[hh * DHv + d];
    }
}

// -------- transpose W[R,Cc] -> out[Cc,R] (tf32) --------
__global__ void transpose_kernel(const float* __restrict__ in, float* __restrict__ out,
                                 int R, int Cc)
{
    __shared__ float tile[32][33];
    int bx = blockIdx.x * 32, by = blockIdx.y * 32;
    int tx = threadIdx.x, ty = threadIdx.y;   // 32x8
    #pragma unroll
    for (int j = 0; j < 32; j += 8)
        tile[ty + j][tx] = in[(size_t)(by + ty + j) * Cc + bx + tx];
    __syncthreads();
    #pragma unroll
    for (int j = 0; j < 32; j += 8)
        out[(size_t)(bx + ty + j) * R + by + tx] = tf32r(tile[tx][ty + j]);
}

// --------- attention collapsed: M = (K^T V) * C^-0.5 per (b,h) ---------
__global__ void ktv_kernel(const float* __restrict__ qkv, float* __restrict__ Mb)
{
    int bh = blockIdx.x;
    int b = bh >> 4, h = bh & 15;
    __shared__ float Ks[32][64], Vs[32][64];
    int tid = threadIdx.x;
    int ty = tid >> 4, tx = tid & 15;
    float acc[4][4];
    #pragma unroll
    for (int i = 0; i < 4; i++)
        #pragma unroll
        for (int j = 0; j < 4; j++) acc[i][j] = 0.f;

    const float* baseK = qkv + (size_t)b * Tv * QKVN + 1024 + h * 64;
    const float* baseV = baseK + 1024;

    for (int t0 = 0; t0 < Tv; t0 += 32) {
        #pragma unroll
        for (int u = 0; u < 2; u++) {
            int idx = tid + 256 * u;
            int r = idx >> 4, c4 = idx & 15;
            *(float4*)&Ks[r][c4*4] = *(const float4*)(baseK + (size_t)(t0 + r) * QKVN + c4 * 4);
            *(float4*)&Vs[r][c4*4] = *(const float4*)(baseV + (size_t)(t0 + r) * QKVN + c4 * 4);
        }
        __syncthreads();
        #pragma unroll
        for (int tt = 0; tt < 32; tt++) {
            float a[4], v[4];
            #pragma unroll
            for (int i = 0; i < 4; i++) a[i] = Ks[tt][ty * 4 + i];
            #pragma unroll
            for (int j = 0; j < 4; j++) v[j] = Vs[tt][tx * 4 + j];
            #pragma unroll
            for (int i = 0; i < 4; i++)
                #pragma unroll
                for (int j = 0; j < 4; j++)
                    acc[i][j] += a[i] * v[j];
        }
        __syncthreads();
    }
    float* out = Mb + (size_t)bh * 4096;
    #pragma unroll
    for (int i = 0; i < 4; i++)
        #pragma unroll
        for (int j = 0; j < 4; j++)
            out[(ty * 4 + i) * 64 + tx * 4 + j] = acc[i][j] * 0.03125f;
}

// --------- heads = Q @ M -> concat layout (tf32-rounded) ---------
__global__ void qm_kernel(const float* __restrict__ qkv, const float* __restrict__ Mb,
                          float* __restrict__ cat)
{
    int bh = blockIdx.y;
    int b = bh >> 4, h = bh & 15;
    int t0 = blockIdx.x * 128;
    __shared__ float Ms[64][64];
    __shared__ float Qs[128][64];
    int tid = threadIdx.x;

    const float* Mp = Mb + (size_t)bh * 4096;
    #pragma unroll
    for (int u = 0; u < 4; u++)
        ((float4*)Ms)[tid + 256 * u] = ((const float4*)Mp)[tid + 256 * u];

    const float* baseQ = qkv + (size_t)b * Tv * QKVN + h * 64;
    #pragma unroll
    for (int u = 0; u < 8; u++) {
        int idx = tid + 256 * u;
        int r = idx >> 4, c4 = idx & 15;
        *(float4*)&Qs[r][c4*4] = *(const float4*)(baseQ + (size_t)(t0 + r) * QKVN + c4 * 4);
    }
    __syncthreads();

    int j = tid & 63, rb = tid >> 6;
    float* outbase = cat + (size_t)(b * Tv + t0) * Cv + h * 64 + j;
    #pragma unroll
    for (int rr = 0; rr < 32; rr++) {
        int row = rb * 32 + rr;
        float acc = 0.f;
        #pragma unroll
        for (int i = 0; i < 64; i++) acc += Qs[row][i] * Ms[i][j];
        outbase[(size_t)row * Cv] = tf32r(acc);
    }
}

// ---------------- launch ----------------
extern "C" void kernel_launch(void* const* d_in, const int* in_sizes, int n_in,
                              void* d_out, int out_size)
{
    (void)in_sizes; (void)n_in; (void)out_size;
    const float* x    = (const float*)d_in[0];
    const float* Wq   = (const float*)d_in[1];
    const float* bq   = (const float*)d_in[2];
    const float* Wk   = (const float*)d_in[3];
    const float* bk   = (const float*)d_in[4];
    const float* Wv   = (const float*)d_in[5];
    const float* bv   = (const float*)d_in[6];
    const float* Wp   = (const float*)d_in[7];
    const float* bp   = (const float*)d_in[8];
    const float* W1   = (const float*)d_in[9];
    const float* b1   = (const float*)d_in[10];
    const float* W2   = (const float*)d_in[11];
    const float* b2   = (const float*)d_in[12];
    const float* ln1w = (const float*)d_in[13];
    const float* ln1b = (const float*)d_in[14];
    const float* ln2w = (const float*)d_in[15];
    const float* ln2b = (const float*)d_in[16];
    float* out = (float*)d_out;

    float *px1, *pqkv, *pWqkv, *pbqkv, *pM, *pcat, *py, *px2, *ph, *pWpT, *pW1T, *pW2T;
    cudaGetSymbolAddress((void**)&px1,   g_x1);
    cudaGetSymbolAddress((void**)&pqkv,  g_qkv);
    cudaGetSymbolAddress((void**)&pWqkv, g_Wqkv);
    cudaGetSymbolAddress((void**)&pbqkv, g_bqkv);
    cudaGetSymbolAddress((void**)&pM,    g_M);
    cudaGetSymbolAddress((void**)&pcat,  g_cat);
    cudaGetSymbolAddress((void**)&py,    g_y);
    cudaGetSymbolAddress((void**)&px2,   g_x2);
    cudaGetSymbolAddress((void**)&ph,    g_h);
    cudaGetSymbolAddress((void**)&pWpT,  g_WpT);
    cudaGetSymbolAddress((void**)&pW1T,  g_W1T);
    cudaGetSymbolAddress((void**)&pW2T,  g_W2T);

    const int smem = NSTAGE * STAGEB;   // 61440
    cudaFuncSetAttribute(mm_gemm<0>, cudaFuncAttributeMaxDynamicSharedMemorySize, smem);
    cudaFuncSetAttribute(mm_gemm<1>, cudaFuncAttributeMaxDynamicSharedMemorySize, smem);
    cudaFuncSetAttribute(mm_gemm<2>, cudaFuncAttributeMaxDynamicSharedMemorySize, smem);

    // weight prep (tf32-rounded, [N,K] layouts)
    pack_kernel<<<(QKVN * Cv + 255) / 256, 256>>>(Wq, Wk, Wv, bq, bk, bv, pWqkv, pbqkv);
    transpose_kernel<<<dim3(Cv/32, Cv/32), dim3(32,8)>>>(Wp, pWpT, Cv, Cv);
    transpose_kernel<<<dim3(Fv/32, Cv/32), dim3(32,8)>>>(W1, pW1T, Cv, Fv);
    transpose_kernel<<<dim3(Cv/32, Fv/32), dim3(32,8)>>>(W2, pW2T, Fv, Cv);

    // x1 = LN1(x)
    ln_kernel<<<BT, 256>>>(x, ln1w, ln1b, px1);
    // qkv = x1 @ Wqkv^T + b        [8192,1024] x [3072,1024]^T
    mm_gemm<0><<<dim3(QKVN/128, BT/128), 256, smem>>>(px1, pWqkv, pbqkv, nullptr, pqkv, BT, QKVN, Cv);
    // attention collapsed
    ktv_kernel<<<Bv * Hv, 256>>>(pqkv, pM);
    qm_kernel<<<dim3(Tv/128, Bv * Hv), 256>>>(pqkv, pM, pcat);
    // y = x1 + cat @ Wp + bp
    mm_gemm<1><<<dim3(Cv/128, BT/128), 256, smem>>>(pcat, pWpT, bp, px1, py, BT, Cv, Cv);
    // x2 = LN2(y)
    ln_kernel<<<BT, 256>>>(py, ln2w, ln2b, px2);
    // h = gelu(x2 @ W1 + b1)
    mm_gemm<2><<<dim3(Fv/128, BT/128), 256, smem>>>(px2, pW1T, b1, nullptr, ph, BT, Fv, Cv);
    // out = x2 + h @ W2 + b2
    mm_gemm<1><<<dim3(Cv/128, BT/128), 256, smem>>>(ph, pW2T, b2, px2, out, BT, Cv, Fv);
}

// round 5
// speedup vs baseline: 3.2723x; 1.7399x over previous
#include <cuda_runtime.h>
#include <math.h>
#include <stdint.h>

// Problem constants
#define Bv 8
#define Tv 1024
#define Cv 1024
#define Hv 16
#define DHv 64
#define Fv 4096
#define BT (Bv*Tv)          // 8192
#define QKVN (3*Cv)         // 3072

// ---------------- scratch ----------------
__device__ float g_x1[BT*Cv];
__device__ float g_qkv[BT*QKVN];
__device__ float g_Wqkv[QKVN*Cv];    // [N=3C, K=C] row-major (K-major operand)
__device__ float g_bqkv[QKVN];
__device__ float g_M[Bv*Hv*DHv*DHv];
__device__ float g_cat[BT*Cv];
__device__ float g_y[BT*Cv];
__device__ float g_x2[BT*Cv];
__device__ float g_h[BT*Fv];
__device__ float g_WpT[Cv*Cv];       // [N=C, K=C]
__device__ float g_W1T[Fv*Cv];       // [N=F, K=C]
__device__ float g_W2T[Cv*Fv];       // [N=C, K=F]

// ---------------- helpers ----------------
__device__ __forceinline__ uint32_t smem_u32(const void* p) {
    uint32_t a;
    asm("{ .reg .u64 t; cvta.to.shared.u64 t, %1; cvt.u32.u64 %0, t; }" : "=r"(a) : "l"(p));
    return a;
}
__device__ __forceinline__ float tf32r(float x) {
    uint32_t u; asm("cvt.rn.tf32.f32 %0, %1;" : "=r"(u) : "f"(x));
    return __uint_as_float(u);
}
__device__ __forceinline__ void cp_async16(uint32_t dst, const void* src) {
    asm volatile("cp.async.cg.shared.global [%0], [%1], 16;" :: "r"(dst), "l"(src) : "memory");
}
__device__ __forceinline__ void cp_commit() { asm volatile("cp.async.commit_group;" ::: "memory"); }
template<int N> __device__ __forceinline__ void cp_wait() {
    asm volatile("cp.async.wait_group %0;" :: "n"(N) : "memory");
}

__device__ __forceinline__ void mma_tf32(float* d, const uint32_t* a, const uint32_t* b) {
    asm volatile(
        "mma.sync.aligned.m16n8k8.row.col.f32.tf32.tf32.f32 "
        "{%0,%1,%2,%3}, {%4,%5,%6,%7}, {%8,%9}, {%0,%1,%2,%3};"
        : "+f"(d[0]), "+f"(d[1]), "+f"(d[2]), "+f"(d[3])
        : "r"(a[0]), "r"(a[1]), "r"(a[2]), "r"(a[3]), "r"(b[0]), "r"(b[1]));
}

__device__ __forceinline__ float gelu_f(float v) {
    return 0.5f * v * (1.0f + erff(v * 0.70710678118654752f));
}

// ---------------- tf32 mma.sync GEMM: C[M,N] = A[M,K] * B^T (B given [N,K]) ----------------
// 128x128 CTA tile, 256 threads (8 warps, 4(M) x 2(N)), warp tile 32x64, BK=32,
// 3-stage cp.async pipeline. SMEM tiles [128][36] floats (conflict-free frag reads:
// bank = (4r + c) mod 32, distinct within each quad-pattern).
// EPI: 0 = +bias ; 1 = +bias+res ; 2 = tf32(gelu(+bias))
#define NSTAGE 3
#define ROWF   36                      // floats per smem row (32 data + 4 pad)
#define TILEF  (128*ROWF)              // 4608 floats
#define TILEB  (TILEF*4)               // 18432 bytes
#define STAGEB (2*TILEB)               // 36864 bytes

template<int EPI>
__global__ __launch_bounds__(256, 2)
void mm_gemm(const float* __restrict__ A, const float* __restrict__ B,
             const float* __restrict__ bias, const float* __restrict__ res,
             float* __restrict__ C, int M, int N, int K)
{
    extern __shared__ float sm[];
    const int tid = threadIdx.x, wid = tid >> 5, lane = tid & 31;
    const int m0 = blockIdx.y * 128, n0 = blockIdx.x * 128;
    const int wm = wid & 3, wn = wid >> 2;        // warp grid 4x2
    const uint32_t sbase = smem_u32(sm);

    // ---- per-thread cp.async slots: 4 A-chunks + 4 B-chunks (16B each) ----
    // A tile 128x32 floats = 1024 chunks of 16B; 256 threads -> 4 chunks each.
    const float* aSrc[4]; uint32_t adst[4];
    const float* bSrc[4]; uint32_t bdst[4];
    #pragma unroll
    for (int u = 0; u < 4; u++) {
        int idx = u * 256 + tid;          // 0..1023
        int row = idx >> 3, c = idx & 7;  // row 0..127, 16B chunk 0..7
        aSrc[u] = A + (size_t)(m0 + row) * K + c * 4;
        bSrc[u] = B + (size_t)(n0 + row) * K + c * 4;
        adst[u] = row * (ROWF * 4) + c * 16;
        bdst[u] = TILEB + adst[u];
    }

    #define ISSUE_STAGE(st, it) do {                                          \
        uint32_t _sb = sbase + (st) * STAGEB;                                 \
        _Pragma("unroll") for (int _u = 0; _u < 4; _u++)                      \
            cp_async16(_sb + adst[_u], aSrc[_u] + (size_t)(it) * 32);         \
        _Pragma("unroll") for (int _u = 0; _u < 4; _u++)                      \
            cp_async16(_sb + bdst[_u], bSrc[_u] + (size_t)(it) * 32);         \
        cp_commit(); } while (0)

    // ---- fragment smem offsets (floats) ----
    int aoff[2], boff[8];
    #pragma unroll
    for (int mi = 0; mi < 2; mi++)
        aoff[mi] = (wm * 32 + mi * 16 + (lane >> 2)) * ROWF + (lane & 3);
    #pragma unroll
    for (int nj = 0; nj < 8; nj++)
        boff[nj] = (wn * 64 + nj * 8 + (lane >> 2)) * ROWF + (lane & 3);

    float acc[2][8][4];
    #pragma unroll
    for (int mi = 0; mi < 2; mi++)
        #pragma unroll
        for (int nj = 0; nj < 8; nj++)
            #pragma unroll
            for (int q = 0; q < 4; q++) acc[mi][nj][q] = 0.f;

    const int NIT = K >> 5;               // BK = 32
    #pragma unroll
    for (int p = 0; p < NSTAGE - 1; p++) ISSUE_STAGE(p, p);

    for (int it = 0; it < NIT; it++) {
        if (it + 1 == NIT) cp_wait<0>(); else cp_wait<NSTAGE - 2>();
        __syncthreads();
        int nit = it + NSTAGE - 1;
        if (nit < NIT) ISSUE_STAGE(nit % NSTAGE, nit);

        const float* sA = sm + (it % NSTAGE) * (STAGEB / 4);
        const float* sB = sA + TILEF;
        #pragma unroll
        for (int kk = 0; kk < 4; kk++) {
            uint32_t af[2][4], bf[8][2];
            #pragma unroll
            for (int mi = 0; mi < 2; mi++) {
                int o = aoff[mi] + kk * 8;
                af[mi][0] = __float_as_uint(sA[o]);
                af[mi][1] = __float_as_uint(sA[o + 8 * ROWF]);
                af[mi][2] = __float_as_uint(sA[o + 4]);
                af[mi][3] = __float_as_uint(sA[o + 8 * ROWF + 4]);
            }
            #pragma unroll
            for (int nj = 0; nj < 8; nj++) {
                int o = boff[nj] + kk * 8;
                bf[nj][0] = __float_as_uint(sB[o]);
                bf[nj][1] = __float_as_uint(sB[o + 4]);
            }
            #pragma unroll
            for (int mi = 0; mi < 2; mi++)
                #pragma unroll
                for (int nj = 0; nj < 8; nj++)
                    mma_tf32(acc[mi][nj], af[mi], bf[nj]);
        }
    }

    // ---- epilogue ----
    #pragma unroll
    for (int mi = 0; mi < 2; mi++) {
        int r0 = m0 + wm * 32 + mi * 16 + (lane >> 2);
        #pragma unroll
        for (int nj = 0; nj < 8; nj++) {
            int cb = n0 + wn * 64 + nj * 8 + (lane & 3) * 2;
            float2 bv = *(const float2*)(bias + cb);
            #pragma unroll
            for (int half = 0; half < 2; half++) {
                int r = r0 + half * 8;
                float vx = acc[mi][nj][half * 2 + 0] + bv.x;
                float vy = acc[mi][nj][half * 2 + 1] + bv.y;
                if (EPI == 1) {
                    float2 rv = *(const float2*)(res + (size_t)r * N + cb);
                    vx += rv.x; vy += rv.y;
                }
                if (EPI == 2) { vx = tf32r(gelu_f(vx)); vy = tf32r(gelu_f(vy)); }
                *(float2*)(C + (size_t)r * N + cb) = make_float2(vx, vy);
            }
        }
    }
    #undef ISSUE_STAGE
}

// ---------------- LayerNorm (tf32-rounded output) ----------------
__global__ void ln_kernel(const float* __restrict__ x, const float* __restrict__ w,
                          const float* __restrict__ bb, float* __restrict__ y)
{
    int row = blockIdx.x;
    int t = threadIdx.x;
    const float4* xr = (const float4*)(x + (size_t)row * Cv);
    float4 v = xr[t];
    float s  = v.x + v.y + v.z + v.w;
    float ss = v.x*v.x + v.y*v.y + v.z*v.z + v.w*v.w;
    #pragma unroll
    for (int o = 16; o > 0; o >>= 1) {
        s  += __shfl_xor_sync(0xffffffffu, s,  o);
        ss += __shfl_xor_sync(0xffffffffu, ss, o);
    }
    __shared__ float shs[8], shss[8], par[2];
    if ((t & 31) == 0) { shs[t >> 5] = s; shss[t >> 5] = ss; }
    __syncthreads();
    if (t == 0) {
        float S = 0.f, SS = 0.f;
        #pragma unroll
        for (int i = 0; i < 8; i++) { S += shs[i]; SS += shss[i]; }
        float mu  = S * (1.0f / 1024.0f);
        float var = SS * (1.0f / 1024.0f) - mu * mu;
        par[0] = mu; par[1] = rsqrtf(var + 1e-3f);
    }
    __syncthreads();
    float mu = par[0], rs = par[1];
    float4 wv = ((const float4*)w)[t];
    float4 bv = ((const float4*)bb)[t];
    float4 o;
    o.x = tf32r((v.x - mu) * rs * wv.x + bv.x);
    o.y = tf32r((v.y - mu) * rs * wv.y + bv.y);
    o.z = tf32r((v.z - mu) * rs * wv.z + bv.z);
    o.w = tf32r((v.w - mu) * rs * wv.w + bv.w);
    ((float4*)(y + (size_t)row * Cv))[t] = o;
}

// -------- pack Wq/Wk/Wv [H,C,Dh] -> [N=3C, K=C] (tf32) + bias --------
__global__ void pack_kernel(const float* __restrict__ Wq, const float* __restrict__ Wk,
                            const float* __restrict__ Wv,
                            const float* __restrict__ bq, const float* __restrict__ bk,
                            const float* __restrict__ bv,
                            float* __restrict__ Wo, float* __restrict__ bo)
{
    int idx = blockIdx.x * 256 + threadIdx.x;       // over 3C*C
    if (idx >= QKVN * Cv) return;
    int n = idx / Cv, k = idx % Cv;
    int sel = n >> 10;
    int hh = (n & 1023) >> 6, d = n & 63;
    const float* W = (sel == 0) ? Wq : (sel == 1) ? Wk : Wv;
    Wo[idx] = tf32r(W[((size_t)hh * Cv + k) * DHv + d]);
    if (k == 0) {
        const float* B = (sel == 0) ? bq : (sel == 1) ? bk : bv;
        bo[n] = B[hh * DHv + d];
    }
}

// -------- transpose W[R,Cc] -> out[Cc,R] (tf32) --------
__global__ void transpose_kernel(const float* __restrict__ in, float* __restrict__ out,
                                 int R, int Cc)
{
    __shared__ float tile[32][33];
    int bx = blockIdx.x * 32, by = blockIdx.y * 32;
    int tx = threadIdx.x, ty = threadIdx.y;   // 32x8
    #pragma unroll
    for (int j = 0; j < 32; j += 8)
        tile[ty + j][tx] = in[(size_t)(by + ty + j) * Cc + bx + tx];
    __syncthreads();
    #pragma unroll
    for (int j = 0; j < 32; j += 8)
        out[(size_t)(bx + ty + j) * R + by + tx] = tf32r(tile[tx][ty + j]);
}

// --------- attention collapsed: M = (K^T V) * C^-0.5 per (b,h) ---------
__global__ void ktv_kernel(const float* __restrict__ qkv, float* __restrict__ Mb)
{
    int bh = blockIdx.x;
    int b = bh >> 4, h = bh & 15;
    __shared__ float Ks[32][64], Vs[32][64];
    int tid = threadIdx.x;
    int ty = tid >> 4, tx = tid & 15;
    float acc[4][4];
    #pragma unroll
    for (int i = 0; i < 4; i++)
        #pragma unroll
        for (int j = 0; j < 4; j++) acc[i][j] = 0.f;

    const float* baseK = qkv + (size_t)b * Tv * QKVN + 1024 + h * 64;
    const float* baseV = baseK + 1024;

    for (int t0 = 0; t0 < Tv; t0 += 32) {
        #pragma unroll
        for (int u = 0; u < 2; u++) {
            int idx = tid + 256 * u;
            int r = idx >> 4, c4 = idx & 15;
            *(float4*)&Ks[r][c4*4] = *(const float4*)(baseK + (size_t)(t0 + r) * QKVN + c4 * 4);
            *(float4*)&Vs[r][c4*4] = *(const float4*)(baseV + (size_t)(t0 + r) * QKVN + c4 * 4);
        }
        __syncthreads();
        #pragma unroll
        for (int tt = 0; tt < 32; tt++) {
            float a[4], v[4];
            #pragma unroll
            for (int i = 0; i < 4; i++) a[i] = Ks[tt][ty * 4 + i];
            #pragma unroll
            for (int j = 0; j < 4; j++) v[j] = Vs[tt][tx * 4 + j];
            #pragma unroll
            for (int i = 0; i < 4; i++)
                #pragma unroll
                for (int j = 0; j < 4; j++)
                    acc[i][j] += a[i] * v[j];
        }
        __syncthreads();
    }
    float* out = Mb + (size_t)bh * 4096;
    #pragma unroll
    for (int i = 0; i < 4; i++)
        #pragma unroll
        for (int j = 0; j < 4; j++)
            out[(ty * 4 + i) * 64 + tx * 4 + j] = acc[i][j] * 0.03125f;
}

// --------- heads = Q @ M -> concat layout (tf32-rounded) ---------
__global__ void qm_kernel(const float* __restrict__ qkv, const float* __restrict__ Mb,
                          float* __restrict__ cat)
{
    int bh = blockIdx.y;
    int b = bh >> 4, h = bh & 15;
    int t0 = blockIdx.x * 128;
    __shared__ float Ms[64][64];
    __shared__ float Qs[128][64];
    int tid = threadIdx.x;

    const float* Mp = Mb + (size_t)bh * 4096;
    #pragma unroll
    for (int u = 0; u < 4; u++)
        ((float4*)Ms)[tid + 256 * u] = ((const float4*)Mp)[tid + 256 * u];

    const float* baseQ = qkv + (size_t)b * Tv * QKVN + h * 64;
    #pragma unroll
    for (int u = 0; u < 8; u++) {
        int idx = tid + 256 * u;
        int r = idx >> 4, c4 = idx & 15;
        *(float4*)&Qs[r][c4*4] = *(const float4*)(baseQ + (size_t)(t0 + r) * QKVN + c4 * 4);
    }
    __syncthreads();

    int j = tid & 63, rb = tid >> 6;
    float* outbase = cat + (size_t)(b * Tv + t0) * Cv + h * 64 + j;
    #pragma unroll
    for (int rr = 0; rr < 32; rr++) {
        int row = rb * 32 + rr;
        float acc = 0.f;
        #pragma unroll
        for (int i = 0; i < 64; i++) acc += Qs[row][i] * Ms[i][j];
        outbase[(size_t)row * Cv] = tf32r(acc);
    }
}

// ---------------- launch ----------------
extern "C" void kernel_launch(void* const* d_in, const int* in_sizes, int n_in,
                              void* d_out, int out_size)
{
    (void)in_sizes; (void)n_in; (void)out_size;
    const float* x    = (const float*)d_in[0];
    const float* Wq   = (const float*)d_in[1];
    const float* bq   = (const float*)d_in[2];
    const float* Wk   = (const float*)d_in[3];
    const float* bk   = (const float*)d_in[4];
    const float* Wv   = (const float*)d_in[5];
    const float* bv   = (const float*)d_in[6];
    const float* Wp   = (const float*)d_in[7];
    const float* bp   = (const float*)d_in[8];
    const float* W1   = (const float*)d_in[9];
    const float* b1   = (const float*)d_in[10];
    const float* W2   = (const float*)d_in[11];
    const float* b2   = (const float*)d_in[12];
    const float* ln1w = (const float*)d_in[13];
    const float* ln1b = (const float*)d_in[14];
    const float* ln2w = (const float*)d_in[15];
    const float* ln2b = (const float*)d_in[16];
    float* out = (float*)d_out;

    float *px1, *pqkv, *pWqkv, *pbqkv, *pM, *pcat, *py, *px2, *ph, *pWpT, *pW1T, *pW2T;
    cudaGetSymbolAddress((void**)&px1,   g_x1);
    cudaGetSymbolAddress((void**)&pqkv,  g_qkv);
    cudaGetSymbolAddress((void**)&pWqkv, g_Wqkv);
    cudaGetSymbolAddress((void**)&pbqkv, g_bqkv);
    cudaGetSymbolAddress((void**)&pM,    g_M);
    cudaGetSymbolAddress((void**)&pcat,  g_cat);
    cudaGetSymbolAddress((void**)&py,    g_y);
    cudaGetSymbolAddress((void**)&px2,   g_x2);
    cudaGetSymbolAddress((void**)&ph,    g_h);
    cudaGetSymbolAddress((void**)&pWpT,  g_WpT);
    cudaGetSymbolAddress((void**)&pW1T,  g_W1T);
    cudaGetSymbolAddress((void**)&pW2T,  g_W2T);

    const int smem = NSTAGE * STAGEB;   // 110592
    cudaFuncSetAttribute(mm_gemm<0>, cudaFuncAttributeMaxDynamicSharedMemorySize, smem);
    cudaFuncSetAttribute(mm_gemm<1>, cudaFuncAttributeMaxDynamicSharedMemorySize, smem);
    cudaFuncSetAttribute(mm_gemm<2>, cudaFuncAttributeMaxDynamicSharedMemorySize, smem);

    // weight prep (tf32-rounded, [N,K] layouts)
    pack_kernel<<<(QKVN * Cv + 255) / 256, 256>>>(Wq, Wk, Wv, bq, bk, bv, pWqkv, pbqkv);
    transpose_kernel<<<dim3(Cv/32, Cv/32), dim3(32,8)>>>(Wp, pWpT, Cv, Cv);
    transpose_kernel<<<dim3(Fv/32, Cv/32), dim3(32,8)>>>(W1, pW1T, Cv, Fv);
    transpose_kernel<<<dim3(Cv/32, Fv/32), dim3(32,8)>>>(W2, pW2T, Fv, Cv);

    // x1 = LN1(x)
    ln_kernel<<<BT, 256>>>(x, ln1w, ln1b, px1);
    // qkv = x1 @ Wqkv^T + b        [8192,1024] x [3072,1024]^T
    mm_gemm<0><<<dim3(QKVN/128, BT/128), 256, smem>>>(px1, pWqkv, pbqkv, nullptr, pqkv, BT, QKVN, Cv);
    // attention collapsed
    ktv_kernel<<<Bv * Hv, 256>>>(pqkv, pM);
    qm_kernel<<<dim3(Tv/128, Bv * Hv), 256>>>(pqkv, pM, pcat);
    // y = x1 + cat @ Wp + bp
    mm_gemm<1><<<dim3(Cv/128, BT/128), 256, smem>>>(pcat, pWpT, bp, px1, py, BT, Cv, Cv);
    // x2 = LN2(y)
    ln_kernel<<<BT, 256>>>(py, ln2w, ln2b, px2);
    // h = gelu(x2 @ W1 + b1)
    mm_gemm<2><<<dim3(Fv/128, BT/128), 256, smem>>>(px2, pW1T, b1, nullptr, ph, BT, Fv, Cv);
    // out = x2 + h @ W2 + b2
    mm_gemm<1><<<dim3(Cv/128, BT/128), 256, smem>>>(ph, pW2T, b2, px2, out, BT, Cv, Fv);
}

// round 7
// speedup vs baseline: 5.8382x; 1.7841x over previous
#include <cuda_runtime.h>
#include <cuda_fp16.h>
#include <math.h>
#include <stdint.h>

// Problem constants
#define Bv 8
#define Tv 1024
#define Cv 1024
#define Hv 16
#define DHv 64
#define Fv 4096
#define BT (Bv*Tv)          // 8192
#define QKVN (3*Cv)         // 3072

// ---------------- scratch ----------------
__device__ float  g_x1[BT*Cv];          // ln1(x) fp32 (residual)
__device__ __half g_x1h[BT*Cv];         // ln1(x) fp16 (GEMM A)
__device__ float  g_qkv[BT*QKVN];       // qkv fp32
__device__ __half g_Wqkvh[QKVN*Cv];     // packed weight [N=3C, K=C] fp16
__device__ float  g_bqkv[QKVN];
__device__ float  g_Mpart[4*128*DHv*DHv]; // partial (K^T V)/32
__device__ __half g_cath[BT*Cv];        // concat heads fp16
__device__ float  g_y[BT*Cv];           // x1 + attn fp32
__device__ float  g_x2[BT*Cv];          // ln2(y) fp32 (residual)
__device__ __half g_x2h[BT*Cv];         // ln2(y) fp16
__device__ __half g_hh[BT*Fv];          // gelu(...) fp16
__device__ __half g_WpTh[Cv*Cv];        // [N=C, K=C] fp16
__device__ __half g_W1Th[Fv*Cv];        // [N=F, K=C] fp16
__device__ __half g_W2Th[Cv*Fv];        // [N=C, K=F] fp16

// ---------------- helpers ----------------
__device__ __forceinline__ uint32_t smem_u32(const void* p) {
    uint32_t a;
    asm("{ .reg .u64 t; cvta.to.shared.u64 t, %1; cvt.u32.u64 %0, t; }" : "=r"(a) : "l"(p));
    return a;
}
__device__ __forceinline__ void cp_async16(uint32_t dst, const void* src) {
    asm volatile("cp.async.cg.shared.global [%0], [%1], 16;" :: "r"(dst), "l"(src) : "memory");
}
__device__ __forceinline__ void cp_commit() { asm volatile("cp.async.commit_group;" ::: "memory"); }
template<int N> __device__ __forceinline__ void cp_wait() {
    asm volatile("cp.async.wait_group %0;" :: "n"(N) : "memory");
}

__device__ __forceinline__ void mma_f16(float* d, const uint32_t* a, const uint32_t* b) {
    asm volatile(
        "mma.sync.aligned.m16n8k16.row.col.f32.f16.f16.f32 "
        "{%0,%1,%2,%3}, {%4,%5,%6,%7}, {%8,%9}, {%0,%1,%2,%3};"
        : "+f"(d[0]), "+f"(d[1]), "+f"(d[2]), "+f"(d[3])
        : "r"(a[0]), "r"(a[1]), "r"(a[2]), "r"(a[3]), "r"(b[0]), "r"(b[1]));
}

__device__ __forceinline__ float gelu_f(float v) {
    return 0.5f * v * (1.0f + erff(v * 0.70710678118654752f));
}

// ---------------- fp16 mma.sync GEMM: C[M,N] = A[M,K] * B^T (B given [N,K] fp16) ----------------
// 128x128 CTA tile, 256 threads (8 warps, 4(M) x 2(N)), warp tile 32x64, BK=64,
// 2-stage cp.async pipeline. SMEM rows 72 halfs (64 data + 8 pad):
//  - STS phases conflict-free; 32-bit frag LDS word index == 4r+c (mod 32) distinct.
// EPI: 0 = +bias ; 1 = +bias+res ; 2 = gelu(+bias). HOUT: 0 -> fp32 C, 1 -> fp16 C.
#define NSTAGE 2
#define ROWH   72                      // halfs per smem row
#define TILEH  (128*ROWH)              // halfs per tile
#define TILEB  (TILEH*2)               // 18432 bytes
#define STAGEB (2*TILEB)               // 36864 bytes

template<int EPI, int HOUT>
__global__ __launch_bounds__(256, 2)
void mm_gemm(const __half* __restrict__ A, const __half* __restrict__ B,
             const float* __restrict__ bias, const float* __restrict__ res,
             void* __restrict__ Cout, int M, int N, int K)
{
    extern __shared__ __half sm[];
    const int tid = threadIdx.x, wid = tid >> 5, lane = tid & 31;
    const int m0 = blockIdx.y * 128, n0 = blockIdx.x * 128;
    const int wm = wid & 3, wn = wid >> 2;        // warp grid 4x2
    const uint32_t sbase = smem_u32(sm);

    // ---- per-thread cp.async slots: 4 A-chunks + 4 B-chunks (16B = 8 halfs each) ----
    // tile 128 rows x 8 chunks = 1024 chunks / 256 threads = 4 each.
    const __half* aSrc[4]; uint32_t adst[4];
    const __half* bSrc[4]; uint32_t bdst[4];
    #pragma unroll
    for (int u = 0; u < 4; u++) {
        int idx = u * 256 + tid;          // 0..1023
        int row = idx >> 3, c = idx & 7;
        aSrc[u] = A + (size_t)(m0 + row) * K + c * 8;
        bSrc[u] = B + (size_t)(n0 + row) * K + c * 8;
        adst[u] = row * (ROWH * 2) + c * 16;
        bdst[u] = TILEB + adst[u];
    }

    #define ISSUE_STAGE(st, it) do {                                          \
        uint32_t _sb = sbase + (st) * STAGEB;                                 \
        _Pragma("unroll") for (int _u = 0; _u < 4; _u++)                      \
            cp_async16(_sb + adst[_u], aSrc[_u] + (size_t)(it) * 64);         \
        _Pragma("unroll") for (int _u = 0; _u < 4; _u++)                      \
            cp_async16(_sb + bdst[_u], bSrc[_u] + (size_t)(it) * 64);         \
        cp_commit(); } while (0)

    // ---- fragment smem offsets (in halfs) ----
    int aoff[2], boff[8];
    #pragma unroll
    for (int mi = 0; mi < 2; mi++)
        aoff[mi] = (wm * 32 + mi * 16 + (lane >> 2)) * ROWH + (lane & 3) * 2;
    #pragma unroll
    for (int nj = 0; nj < 8; nj++)
        boff[nj] = (wn * 64 + nj * 8 + (lane >> 2)) * ROWH + (lane & 3) * 2;

    float acc[2][8][4];
    #pragma unroll
    for (int mi = 0; mi < 2; mi++)
        #pragma unroll
        for (int nj = 0; nj < 8; nj++)
            #pragma unroll
            for (int q = 0; q < 4; q++) acc[mi][nj][q] = 0.f;

    const int NIT = K >> 6;               // BK = 64
    ISSUE_STAGE(0, 0);

    for (int it = 0; it < NIT; it++) {
        cp_wait<0>();
        __syncthreads();
        if (it + 1 < NIT) ISSUE_STAGE((it + 1) & 1, it + 1);

        const __half* sA = sm + (it & 1) * (STAGEB / 2);
        const __half* sB = sA + TILEH;
        #pragma unroll
        for (int kk = 0; kk < 4; kk++) {            // 4 x k16
            uint32_t af[2][4], bf[8][2];
            #pragma unroll
            for (int mi = 0; mi < 2; mi++) {
                int o = aoff[mi] + kk * 16;
                af[mi][0] = *(const uint32_t*)(sA + o);
                af[mi][1] = *(const uint32_t*)(sA + o + 8 * ROWH);
                af[mi][2] = *(const uint32_t*)(sA + o + 8);
                af[mi][3] = *(const uint32_t*)(sA + o + 8 * ROWH + 8);
            }
            #pragma unroll
            for (int nj = 0; nj < 8; nj++) {
                int o = boff[nj] + kk * 16;
                bf[nj][0] = *(const uint32_t*)(sB + o);
                bf[nj][1] = *(const uint32_t*)(sB + o + 8);
            }
            #pragma unroll
            for (int mi = 0; mi < 2; mi++)
                #pragma unroll
                for (int nj = 0; nj < 8; nj++)
                    mma_f16(acc[mi][nj], af[mi], bf[nj]);
        }
    }

    // ---- epilogue ----
    #pragma unroll
    for (int mi = 0; mi < 2; mi++) {
        int r0 = m0 + wm * 32 + mi * 16 + (lane >> 2);
        #pragma unroll
        for (int nj = 0; nj < 8; nj++) {
            int cb = n0 + wn * 64 + nj * 8 + (lane & 3) * 2;
            float2 bv = *(const float2*)(bias + cb);
            #pragma unroll
            for (int half_ = 0; half_ < 2; half_++) {
                int r = r0 + half_ * 8;
                float vx = acc[mi][nj][half_ * 2 + 0] + bv.x;
                float vy = acc[mi][nj][half_ * 2 + 1] + bv.y;
                if (EPI == 1) {
                    float2 rv = *(const float2*)(res + (size_t)r * N + cb);
                    vx += rv.x; vy += rv.y;
                }
                if (EPI == 2) { vx = gelu_f(vx); vy = gelu_f(vy); }
                if (HOUT) {
                    *(__half2*)((__half*)Cout + (size_t)r * N + cb) = __floats2half2_rn(vx, vy);
                } else {
                    *(float2*)((float*)Cout + (size_t)r * N + cb) = make_float2(vx, vy);
                }
            }
        }
    }
    #undef ISSUE_STAGE
}

// ---------------- LayerNorm: fp32 + fp16 outputs ----------------
__global__ void ln_kernel(const float* __restrict__ x, const float* __restrict__ w,
                          const float* __restrict__ bb,
                          float* __restrict__ y, __half* __restrict__ yh)
{
    int row = blockIdx.x;
    int t = threadIdx.x;
    const float4* xr = (const float4*)(x + (size_t)row * Cv);
    float4 v = xr[t];
    float s  = v.x + v.y + v.z + v.w;
    float ss = v.x*v.x + v.y*v.y + v.z*v.z + v.w*v.w;
    #pragma unroll
    for (int o = 16; o > 0; o >>= 1) {
        s  += __shfl_xor_sync(0xffffffffu, s,  o);
        ss += __shfl_xor_sync(0xffffffffu, ss, o);
    }
    __shared__ float shs[8], shss[8], par[2];
    if ((t & 31) == 0) { shs[t >> 5] = s; shss[t >> 5] = ss; }
    __syncthreads();
    if (t == 0) {
        float S = 0.f, SS = 0.f;
        #pragma unroll
        for (int i = 0; i < 8; i++) { S += shs[i]; SS += shss[i]; }
        float mu  = S * (1.0f / 1024.0f);
        float var = SS * (1.0f / 1024.0f) - mu * mu;
        par[0] = mu; par[1] = rsqrtf(var + 1e-3f);
    }
    __syncthreads();
    float mu = par[0], rs = par[1];
    float4 wv = ((const float4*)w)[t];
    float4 bv = ((const float4*)bb)[t];
    float4 o;
    o.x = (v.x - mu) * rs * wv.x + bv.x;
    o.y = (v.y - mu) * rs * wv.y + bv.y;
    o.z = (v.z - mu) * rs * wv.z + bv.z;
    o.w = (v.w - mu) * rs * wv.w + bv.w;
    ((float4*)(y + (size_t)row * Cv))[t] = o;
    __half2* yh2 = (__half2*)(yh + (size_t)row * Cv);
    yh2[2 * t + 0] = __floats2half2_rn(o.x, o.y);
    yh2[2 * t + 1] = __floats2half2_rn(o.z, o.w);
}

// -------- pack Wq/Wk/Wv [H,C,Dh] -> [N=3C, K=C] fp16 + bias fp32 --------
__global__ void pack_kernel(const float* __restrict__ Wq, const float* __restrict__ Wk,
                            const float* __restrict__ Wv,
                            const float* __restrict__ bq, const float* __restrict__ bk,
                            const float* __restrict__ bv,
                            __half* __restrict__ Wo, float* __restrict__ bo)
{
    int idx = blockIdx.x * 256 + threadIdx.x;       // over 3C*C
    if (idx >= QKVN * Cv) return;
    int n = idx / Cv, k = idx % Cv;
    int sel = n >> 10;
    int hh = (n & 1023) >> 6, d = n & 63;
    const float* W = (sel == 0) ? Wq : (sel == 1) ? Wk : Wv;
    Wo[idx] = __float2half(W[((size_t)hh * Cv + k) * DHv + d]);
    if (k == 0) {
        const float* B = (sel == 0) ? bq : (sel == 1) ? bk : bv;
        bo[n] = B[hh * DHv + d];
    }
}

// -------- transpose W[R,Cc] -> out[Cc,R] fp16 --------
__global__ void transpose_kernel(const float* __restrict__ in, __half* __restrict__ out,
                                 int R, int Cc)
{
    __shared__ float tile[32][33];
    int bx = blockIdx.x * 32, by = blockIdx.y * 32;
    int tx = threadIdx.x, ty = threadIdx.y;   // 32x8
    #pragma unroll
    for (int j = 0; j < 32; j += 8)
        tile[ty + j][tx] = in[(size_t)(by + ty + j) * Cc + bx + tx];
    __syncthreads();
    #pragma unroll
    for (int j = 0; j < 32; j += 8)
        out[(size_t)(bx + ty + j) * R + by + tx] = __float2half(tile[tx][ty + j]);
}

// --------- attention collapsed: Mpart[p] = (K[p]^T V[p]) * C^-0.5, p = T-quarter ---------
__global__ void ktv_kernel(const float* __restrict__ qkv, float* __restrict__ Mp)
{
    int bh = blockIdx.x;               // 128
    int part = blockIdx.y;             // 4
    int b = bh >> 4, h = bh & 15;
    __shared__ float Ks[32][64], Vs[32][64];
    int tid = threadIdx.x;
    int ty = tid >> 4, tx = tid & 15;
    float acc[4][4];
    #pragma unroll
    for (int i = 0; i < 4; i++)
        #pragma unroll
        for (int j = 0; j < 4; j++) acc[i][j] = 0.f;

    const float* baseK = qkv + (size_t)b * Tv * QKVN + 1024 + h * 64;
    const float* baseV = baseK + 1024;
    int tlo = part * 256, thi = tlo + 256;

    for (int t0 = tlo; t0 < thi; t0 += 32) {
        #pragma unroll
        for (int u = 0; u < 2; u++) {
            int idx = tid + 256 * u;
            int r = idx >> 4, c4 = idx & 15;
            *(float4*)&Ks[r][c4*4] = *(const float4*)(baseK + (size_t)(t0 + r) * QKVN + c4 * 4);
            *(float4*)&Vs[r][c4*4] = *(const float4*)(baseV + (size_t)(t0 + r) * QKVN + c4 * 4);
        }
        __syncthreads();
        #pragma unroll
        for (int tt = 0; tt < 32; tt++) {
            float a[4], v[4];
            #pragma unroll
            for (int i = 0; i < 4; i++) a[i] = Ks[tt][ty * 4 + i];
            #pragma unroll
            for (int j = 0; j < 4; j++) v[j] = Vs[tt][tx * 4 + j];
            #pragma unroll
            for (int i = 0; i < 4; i++)
                #pragma unroll
                for (int j = 0; j < 4; j++)
                    acc[i][j] += a[i] * v[j];
        }
        __syncthreads();
    }
    float* out = Mp + ((size_t)part * 128 + bh) * 4096;
    #pragma unroll
    for (int i = 0; i < 4; i++)
        #pragma unroll
        for (int j = 0; j < 4; j++)
            out[(ty * 4 + i) * 64 + tx * 4 + j] = acc[i][j] * 0.03125f;
}

// --------- heads = Q @ M -> concat layout (fp16) ---------
__global__ void qm_kernel(const float* __restrict__ qkv, const float* __restrict__ Mp,
                          __half* __restrict__ cat)
{
    int bh = blockIdx.y;
    int b = bh >> 4, h = bh & 15;
    int t0 = blockIdx.x * 128;
    __shared__ float Ms[64][64];
    __shared__ float Qs[128][64];
    int tid = threadIdx.x;

    const float4* p0 = (const float4*)(Mp + ((size_t)0 * 128 + bh) * 4096);
    const float4* p1 = (const float4*)(Mp + ((size_t)1 * 128 + bh) * 4096);
    const float4* p2 = (const float4*)(Mp + ((size_t)2 * 128 + bh) * 4096);
    const float4* p3 = (const float4*)(Mp + ((size_t)3 * 128 + bh) * 4096);
    #pragma unroll
    for (int u = 0; u < 4; u++) {
        int i = tid + 256 * u;
        float4 a = p0[i], c = p1[i], d = p2[i], e = p3[i];
        a.x += c.x + d.x + e.x; a.y += c.y + d.y + e.y;
        a.z += c.z + d.z + e.z; a.w += c.w + d.w + e.w;
        ((float4*)Ms)[i] = a;
    }

    const float* baseQ = qkv + (size_t)b * Tv * QKVN + h * 64;
    #pragma unroll
    for (int u = 0; u < 8; u++) {
        int idx = tid + 256 * u;
        int r = idx >> 4, c4 = idx & 15;
        *(float4*)&Qs[r][c4*4] = *(const float4*)(baseQ + (size_t)(t0 + r) * QKVN + c4 * 4);
    }
    __syncthreads();

    int j = tid & 63, rb = tid >> 6;
    __half* outbase = cat + (size_t)(b * Tv + t0) * Cv + h * 64 + j;
    #pragma unroll
    for (int rr = 0; rr < 32; rr++) {
        int row = rb * 32 + rr;
        float acc = 0.f;
        #pragma unroll
        for (int i = 0; i < 64; i++) acc += Qs[row][i] * Ms[i][j];
        outbase[(size_t)row * Cv] = __float2half(acc);
    }
}

// ---------------- launch ----------------
extern "C" void kernel_launch(void* const* d_in, const int* in_sizes, int n_in,
                              void* d_out, int out_size)
{
    (void)in_sizes; (void)n_in; (void)out_size;
    const float* x    = (const float*)d_in[0];
    const float* Wq   = (const float*)d_in[1];
    const float* bq   = (const float*)d_in[2];
    const float* Wk   = (const float*)d_in[3];
    const float* bk   = (const float*)d_in[4];
    const float* Wv   = (const float*)d_in[5];
    const float* bv   = (const float*)d_in[6];
    const float* Wp   = (const float*)d_in[7];
    const float* bp   = (const float*)d_in[8];
    const float* W1   = (const float*)d_in[9];
    const float* b1   = (const float*)d_in[10];
    const float* W2   = (const float*)d_in[11];
    const float* b2   = (const float*)d_in[12];
    const float* ln1w = (const float*)d_in[13];
    const float* ln1b = (const float*)d_in[14];
    const float* ln2w = (const float*)d_in[15];
    const float* ln2b = (const float*)d_in[16];
    float* out = (float*)d_out;

    float *px1, *pqkv, *pbqkv, *pMp, *py, *px2;
    __half *px1h, *pWqkvh, *pcath, *px2h, *phh, *pWpTh, *pW1Th, *pW2Th;
    cudaGetSymbolAddress((void**)&px1,    g_x1);
    cudaGetSymbolAddress((void**)&px1h,   g_x1h);
    cudaGetSymbolAddress((void**)&pqkv,   g_qkv);
    cudaGetSymbolAddress((void**)&pWqkvh, g_Wqkvh);
    cudaGetSymbolAddress((void**)&pbqkv,  g_bqkv);
    cudaGetSymbolAddress((void**)&pMp,    g_Mpart);
    cudaGetSymbolAddress((void**)&pcath,  g_cath);
    cudaGetSymbolAddress((void**)&py,     g_y);
    cudaGetSymbolAddress((void**)&px2,    g_x2);
    cudaGetSymbolAddress((void**)&px2h,   g_x2h);
    cudaGetSymbolAddress((void**)&phh,    g_hh);
    cudaGetSymbolAddress((void**)&pWpTh,  g_WpTh);
    cudaGetSymbolAddress((void**)&pW1Th,  g_W1Th);
    cudaGetSymbolAddress((void**)&pW2Th,  g_W2Th);

    const int smem = NSTAGE * STAGEB;   // 73728
    cudaFuncSetAttribute(mm_gemm<0,0>, cudaFuncAttributeMaxDynamicSharedMemorySize, smem);
    cudaFuncSetAttribute(mm_gemm<1,0>, cudaFuncAttributeMaxDynamicSharedMemorySize, smem);
    cudaFuncSetAttribute(mm_gemm<2,1>, cudaFuncAttributeMaxDynamicSharedMemorySize, smem);

    // weight prep (fp16, [N,K] layouts)
    pack_kernel<<<(QKVN * Cv + 255) / 256, 256>>>(Wq, Wk, Wv, bq, bk, bv, pWqkvh, pbqkv);
    transpose_kernel<<<dim3(Cv/32, Cv/32), dim3(32,8)>>>(Wp, pWpTh, Cv, Cv);
    transpose_kernel<<<dim3(Fv/32, Cv/32), dim3(32,8)>>>(W1, pW1Th, Cv, Fv);
    transpose_kernel<<<dim3(Cv/32, Fv/32), dim3(32,8)>>>(W2, pW2Th, Fv, Cv);

    // x1 = LN1(x) (fp32 + fp16)
    ln_kernel<<<BT, 256>>>(x, ln1w, ln1b, px1, px1h);
    // qkv = x1 @ Wqkv^T + b        [8192,1024] x [3072,1024]^T -> fp32
    mm_gemm<0,0><<<dim3(QKVN/128, BT/128), 256, smem>>>(px1h, pWqkvh, pbqkv, nullptr, pqkv, BT, QKVN, Cv);
    // attention collapsed (4-way T split + qm-side reduce)
    ktv_kernel<<<dim3(Bv * Hv, 4), 256>>>(pqkv, pMp);
    qm_kernel<<<dim3(Tv/128, Bv * Hv), 256>>>(pqkv, pMp, pcath);
    // y = x1 + cat @ Wp + bp   -> fp32
    mm_gemm<1,0><<<dim3(Cv/128, BT/128), 256, smem>>>(pcath, pWpTh, bp, px1, py, BT, Cv, Cv);
    // x2 = LN2(y) (fp32 + fp16)
    ln_kernel<<<BT, 256>>>(py, ln2w, ln2b, px2, px2h);
    // h = gelu(x2 @ W1 + b1)   -> fp16
    mm_gemm<2,1><<<dim3(Fv/128, BT/128), 256, smem>>>(px2h, pW1Th, b1, nullptr, phh, BT, Fv, Cv);
    // out = x2 + h @ W2 + b2   -> fp32
    mm_gemm<1,0><<<dim3(Cv/128, BT/128), 256, smem>>>(phh, pW2Th, b2, px2, out, BT, Cv, Fv);
}

// round 8
// speedup vs baseline: 5.8622x; 1.0041x over previous
#include <cuda_runtime.h>
#include <cuda_fp16.h>
#include <math.h>
#include <stdint.h>

// Problem constants
#define Bv 8
#define Tv 1024
#define Cv 1024
#define Hv 16
#define DHv 64
#define Fv 4096
#define BT (Bv*Tv)          // 8192
#define QKVN (3*Cv)         // 3072

// ---------------- scratch ----------------
__device__ float  g_x1[BT*Cv];          // ln1(x) fp32 (residual)
__device__ __half g_x1h[BT*Cv];         // ln1(x) fp16 (GEMM A)
__device__ __half g_qkvh[BT*QKVN];      // qkv fp16
__device__ __half g_Wqkvh[QKVN*Cv];     // packed weight [N=3C, K=C] fp16
__device__ float  g_bqkv[QKVN];
__device__ float  g_Mpart[4*128*DHv*DHv]; // partial (K^T V)/32
__device__ __half g_cath[BT*Cv];        // concat heads fp16
__device__ float  g_y[BT*Cv];           // x1 + attn fp32
__device__ float  g_x2[BT*Cv];          // ln2(y) fp32 (residual)
__device__ __half g_x2h[BT*Cv];         // ln2(y) fp16
__device__ __half g_hh[BT*Fv];          // gelu(...) fp16
__device__ __half g_WpTh[Cv*Cv];        // [N=C, K=C] fp16
__device__ __half g_W1Th[Fv*Cv];        // [N=F, K=C] fp16
__device__ __half g_W2Th[Cv*Fv];        // [N=C, K=F] fp16

// ---------------- helpers ----------------
__device__ __forceinline__ uint32_t smem_u32(const void* p) {
    uint32_t a;
    asm("{ .reg .u64 t; cvta.to.shared.u64 t, %1; cvt.u32.u64 %0, t; }" : "=r"(a) : "l"(p));
    return a;
}
__device__ __forceinline__ void cp_async16(uint32_t dst, const void* src) {
    asm volatile("cp.async.cg.shared.global [%0], [%1], 16;" :: "r"(dst), "l"(src) : "memory");
}
__device__ __forceinline__ void cp_commit() { asm volatile("cp.async.commit_group;" ::: "memory"); }
template<int N> __device__ __forceinline__ void cp_wait() {
    asm volatile("cp.async.wait_group %0;" :: "n"(N) : "memory");
}

__device__ __forceinline__ void mma_f16(float* d, const uint32_t* a, const uint32_t* b) {
    asm volatile(
        "mma.sync.aligned.m16n8k16.row.col.f32.f16.f16.f32 "
        "{%0,%1,%2,%3}, {%4,%5,%6,%7}, {%8,%9}, {%0,%1,%2,%3};"
        : "+f"(d[0]), "+f"(d[1]), "+f"(d[2]), "+f"(d[3])
        : "r"(a[0]), "r"(a[1]), "r"(a[2]), "r"(a[3]), "r"(b[0]), "r"(b[1]));
}

__device__ __forceinline__ float gelu_f(float v) {
    return 0.5f * v * (1.0f + erff(v * 0.70710678118654752f));
}

// ---------------- fp16 mma.sync GEMM: C[M,N] = A[M,K] * B^T (B given [N,K] fp16) ----------------
// 128x128 CTA tile, 256 threads (8 warps, 4(M) x 2(N)), warp tile 32x64, BK=64,
// 2-stage cp.async pipeline. SMEM rows 72 halfs (64 data + 8 pad).
// EPI: 0 = +bias ; 1 = +bias+res ; 2 = gelu(+bias). HOUT: 0 -> fp32 C, 1 -> fp16 C.
#define NSTAGE 2
#define ROWH   72                      // halfs per smem row
#define TILEH  (128*ROWH)              // halfs per tile
#define TILEB  (TILEH*2)               // 18432 bytes
#define STAGEB (2*TILEB)               // 36864 bytes

template<int EPI, int HOUT>
__global__ __launch_bounds__(256, 2)
void mm_gemm(const __half* __restrict__ A, const __half* __restrict__ B,
             const float* __restrict__ bias, const float* __restrict__ res,
             void* __restrict__ Cout, int M, int N, int K)
{
    extern __shared__ __half sm[];
    const int tid = threadIdx.x, wid = tid >> 5, lane = tid & 31;
    const int m0 = blockIdx.y * 128, n0 = blockIdx.x * 128;
    const int wm = wid & 3, wn = wid >> 2;        // warp grid 4x2
    const uint32_t sbase = smem_u32(sm);

    // ---- per-thread cp.async slots: 4 A-chunks + 4 B-chunks (16B = 8 halfs each) ----
    const __half* aSrc[4]; uint32_t adst[4];
    const __half* bSrc[4]; uint32_t bdst[4];
    #pragma unroll
    for (int u = 0; u < 4; u++) {
        int idx = u * 256 + tid;          // 0..1023
        int row = idx >> 3, c = idx & 7;
        aSrc[u] = A + (size_t)(m0 + row) * K + c * 8;
        bSrc[u] = B + (size_t)(n0 + row) * K + c * 8;
        adst[u] = row * (ROWH * 2) + c * 16;
        bdst[u] = TILEB + adst[u];
    }

    #define ISSUE_STAGE(st, it) do {                                          \
        uint32_t _sb = sbase + (st) * STAGEB;                                 \
        _Pragma("unroll") for (int _u = 0; _u < 4; _u++)                      \
            cp_async16(_sb + adst[_u], aSrc[_u] + (size_t)(it) * 64);         \
        _Pragma("unroll") for (int _u = 0; _u < 4; _u++)                      \
            cp_async16(_sb + bdst[_u], bSrc[_u] + (size_t)(it) * 64);         \
        cp_commit(); } while (0)

    // ---- fragment smem offsets (in halfs) ----
    int aoff[2], boff[8];
    #pragma unroll
    for (int mi = 0; mi < 2; mi++)
        aoff[mi] = (wm * 32 + mi * 16 + (lane >> 2)) * ROWH + (lane & 3) * 2;
    #pragma unroll
    for (int nj = 0; nj < 8; nj++)
        boff[nj] = (wn * 64 + nj * 8 + (lane >> 2)) * ROWH + (lane & 3) * 2;

    float acc[2][8][4];
    #pragma unroll
    for (int mi = 0; mi < 2; mi++)
        #pragma unroll
        for (int nj = 0; nj < 8; nj++)
            #pragma unroll
            for (int q = 0; q < 4; q++) acc[mi][nj][q] = 0.f;

    const int NIT = K >> 6;               // BK = 64
    ISSUE_STAGE(0, 0);

    for (int it = 0; it < NIT; it++) {
        cp_wait<0>();
        __syncthreads();
        if (it + 1 < NIT) ISSUE_STAGE((it + 1) & 1, it + 1);

        const __half* sA = sm + (it & 1) * (STAGEB / 2);
        const __half* sB = sA + TILEH;
        #pragma unroll
        for (int kk = 0; kk < 4; kk++) {            // 4 x k16
            uint32_t af[2][4], bf[8][2];
            #pragma unroll
            for (int mi = 0; mi < 2; mi++) {
                int o = aoff[mi] + kk * 16;
                af[mi][0] = *(const uint32_t*)(sA + o);
                af[mi][1] = *(const uint32_t*)(sA + o + 8 * ROWH);
                af[mi][2] = *(const uint32_t*)(sA + o + 8);
                af[mi][3] = *(const uint32_t*)(sA + o + 8 * ROWH + 8);
            }
            #pragma unroll
            for (int nj = 0; nj < 8; nj++) {
                int o = boff[nj] + kk * 16;
                bf[nj][0] = *(const uint32_t*)(sB + o);
                bf[nj][1] = *(const uint32_t*)(sB + o + 8);
            }
            #pragma unroll
            for (int mi = 0; mi < 2; mi++)
                #pragma unroll
                for (int nj = 0; nj < 8; nj++)
                    mma_f16(acc[mi][nj], af[mi], bf[nj]);
        }
    }

    // ---- epilogue ----
    #pragma unroll
    for (int mi = 0; mi < 2; mi++) {
        int r0 = m0 + wm * 32 + mi * 16 + (lane >> 2);
        #pragma unroll
        for (int nj = 0; nj < 8; nj++) {
            int cb = n0 + wn * 64 + nj * 8 + (lane & 3) * 2;
            float2 bv = *(const float2*)(bias + cb);
            #pragma unroll
            for (int half_ = 0; half_ < 2; half_++) {
                int r = r0 + half_ * 8;
                float vx = acc[mi][nj][half_ * 2 + 0] + bv.x;
                float vy = acc[mi][nj][half_ * 2 + 1] + bv.y;
                if (EPI == 1) {
                    float2 rv = *(const float2*)(res + (size_t)r * N + cb);
                    vx += rv.x; vy += rv.y;
                }
                if (EPI == 2) { vx = gelu_f(vx); vy = gelu_f(vy); }
                if (HOUT) {
                    *(__half2*)((__half*)Cout + (size_t)r * N + cb) = __floats2half2_rn(vx, vy);
                } else {
                    *(float2*)((float*)Cout + (size_t)r * N + cb) = make_float2(vx, vy);
                }
            }
        }
    }
    #undef ISSUE_STAGE
}

// ---------------- LayerNorm: fp32 + fp16 outputs ----------------
__global__ void ln_kernel(const float* __restrict__ x, const float* __restrict__ w,
                          const float* __restrict__ bb,
                          float* __restrict__ y, __half* __restrict__ yh)
{
    int row = blockIdx.x;
    int t = threadIdx.x;
    const float4* xr = (const float4*)(x + (size_t)row * Cv);
    float4 v = xr[t];
    float s  = v.x + v.y + v.z + v.w;
    float ss = v.x*v.x + v.y*v.y + v.z*v.z + v.w*v.w;
    #pragma unroll
    for (int o = 16; o > 0; o >>= 1) {
        s  += __shfl_xor_sync(0xffffffffu, s,  o);
        ss += __shfl_xor_sync(0xffffffffu, ss, o);
    }
    __shared__ float shs[8], shss[8], par[2];
    if ((t & 31) == 0) { shs[t >> 5] = s; shss[t >> 5] = ss; }
    __syncthreads();
    if (t == 0) {
        float S = 0.f, SS = 0.f;
        #pragma unroll
        for (int i = 0; i < 8; i++) { S += shs[i]; SS += shss[i]; }
        float mu  = S * (1.0f / 1024.0f);
        float var = SS * (1.0f / 1024.0f) - mu * mu;
        par[0] = mu; par[1] = rsqrtf(var + 1e-3f);
    }
    __syncthreads();
    float mu = par[0], rs = par[1];
    float4 wv = ((const float4*)w)[t];
    float4 bv = ((const float4*)bb)[t];
    float4 o;
    o.x = (v.x - mu) * rs * wv.x + bv.x;
    o.y = (v.y - mu) * rs * wv.y + bv.y;
    o.z = (v.z - mu) * rs * wv.z + bv.z;
    o.w = (v.w - mu) * rs * wv.w + bv.w;
    ((float4*)(y + (size_t)row * Cv))[t] = o;
    __half2* yh2 = (__half2*)(yh + (size_t)row * Cv);
    yh2[2 * t + 0] = __floats2half2_rn(o.x, o.y);
    yh2[2 * t + 1] = __floats2half2_rn(o.z, o.w);
}

// -------- pack Wq/Wk/Wv [H,C,Dh] -> [N=3C, K=C] fp16 + bias fp32 --------
__global__ void pack_kernel(const float* __restrict__ Wq, const float* __restrict__ Wk,
                            const float* __restrict__ Wv,
                            const float* __restrict__ bq, const float* __restrict__ bk,
                            const float* __restrict__ bv,
                            __half* __restrict__ Wo, float* __restrict__ bo)
{
    int idx = blockIdx.x * 256 + threadIdx.x;       // over 3C*C
    if (idx >= QKVN * Cv) return;
    int n = idx / Cv, k = idx % Cv;
    int sel = n >> 10;
    int hh = (n & 1023) >> 6, d = n & 63;
    const float* W = (sel == 0) ? Wq : (sel == 1) ? Wk : Wv;
    Wo[idx] = __float2half(W[((size_t)hh * Cv + k) * DHv + d]);
    if (k == 0) {
        const float* B = (sel == 0) ? bq : (sel == 1) ? bk : bv;
        bo[n] = B[hh * DHv + d];
    }
}

// -------- transpose W[R,Cc] -> out[Cc,R] fp16 --------
__global__ void transpose_kernel(const float* __restrict__ in, __half* __restrict__ out,
                                 int R, int Cc)
{
    __shared__ float tile[32][33];
    int bx = blockIdx.x * 32, by = blockIdx.y * 32;
    int tx = threadIdx.x, ty = threadIdx.y;   // 32x8
    #pragma unroll
    for (int j = 0; j < 32; j += 8)
        tile[ty + j][tx] = in[(size_t)(by + ty + j) * Cc + bx + tx];
    __syncthreads();
    #pragma unroll
    for (int j = 0; j < 32; j += 8)
        out[(size_t)(bx + ty + j) * R + by + tx] = __float2half(tile[tx][ty + j]);
}

// --------- attention collapsed: Mpart[p] = (K[p]^T V[p]) * C^-0.5, fp16 inputs ---------
__global__ void ktv_kernel(const __half* __restrict__ qkv, float* __restrict__ Mp)
{
    int bh = blockIdx.x;               // 128
    int part = blockIdx.y;             // 4
    int b = bh >> 4, h = bh & 15;
    __shared__ float Ks[32][64], Vs[32][64];
    int tid = threadIdx.x;
    int ty = tid >> 4, tx = tid & 15;
    float acc[4][4];
    #pragma unroll
    for (int i = 0; i < 4; i++)
        #pragma unroll
        for (int j = 0; j < 4; j++) acc[i][j] = 0.f;

    const __half* baseK = qkv + (size_t)b * Tv * QKVN + 1024 + h * 64;
    const __half* baseV = baseK + 1024;
    int tlo = part * 256, thi = tlo + 256;

    for (int t0 = tlo; t0 < thi; t0 += 32) {
        // 32 rows x 64 halfs = 1024 half2 per tile; 256 threads -> 4 half2 each
        #pragma unroll
        for (int u = 0; u < 4; u++) {
            int idx = tid + 256 * u;            // 0..1023
            int r = idx >> 5, c2 = idx & 31;    // row, half2 index
            __half2 kv = *(const __half2*)(baseK + (size_t)(t0 + r) * QKVN + c2 * 2);
            __half2 vv = *(const __half2*)(baseV + (size_t)(t0 + r) * QKVN + c2 * 2);
            float2 kf = __half22float2(kv), vf = __half22float2(vv);
            Ks[r][c2 * 2] = kf.x; Ks[r][c2 * 2 + 1] = kf.y;
            Vs[r][c2 * 2] = vf.x; Vs[r][c2 * 2 + 1] = vf.y;
        }
        __syncthreads();
        #pragma unroll
        for (int tt = 0; tt < 32; tt++) {
            float a[4], v[4];
            #pragma unroll
            for (int i = 0; i < 4; i++) a[i] = Ks[tt][ty * 4 + i];
            #pragma unroll
            for (int j = 0; j < 4; j++) v[j] = Vs[tt][tx * 4 + j];
            #pragma unroll
            for (int i = 0; i < 4; i++)
                #pragma unroll
                for (int j = 0; j < 4; j++)
                    acc[i][j] += a[i] * v[j];
        }
        __syncthreads();
    }
    float* out = Mp + ((size_t)part * 128 + bh) * 4096;
    #pragma unroll
    for (int i = 0; i < 4; i++)
        #pragma unroll
        for (int j = 0; j < 4; j++)
            out[(ty * 4 + i) * 64 + tx * 4 + j] = acc[i][j] * 0.03125f;
}

// --------- heads = Q @ M -> concat layout (fp16 in/out) ---------
__global__ void qm_kernel(const __half* __restrict__ qkv, const float* __restrict__ Mp,
                          __half* __restrict__ cat)
{
    int bh = blockIdx.y;
    int b = bh >> 4, h = bh & 15;
    int t0 = blockIdx.x * 128;
    __shared__ float Ms[64][64];
    __shared__ float Qs[128][64];
    int tid = threadIdx.x;

    const float4* p0 = (const float4*)(Mp + ((size_t)0 * 128 + bh) * 4096);
    const float4* p1 = (const float4*)(Mp + ((size_t)1 * 128 + bh) * 4096);
    const float4* p2 = (const float4*)(Mp + ((size_t)2 * 128 + bh) * 4096);
    const float4* p3 = (const float4*)(Mp + ((size_t)3 * 128 + bh) * 4096);
    #pragma unroll
    for (int u = 0; u < 4; u++) {
        int i = tid + 256 * u;
        float4 a = p0[i], c = p1[i], d = p2[i], e = p3[i];
        a.x += c.x + d.x + e.x; a.y += c.y + d.y + e.y;
        a.z += c.z + d.z + e.z; a.w += c.w + d.w + e.w;
        ((float4*)Ms)[i] = a;
    }

    const __half* baseQ = qkv + (size_t)b * Tv * QKVN + h * 64;
    // 128 rows x 64 halfs = 4096 half2; 256 threads -> 16 half2 each
    #pragma unroll
    for (int u = 0; u < 16; u++) {
        int idx = tid + 256 * u;            // 0..4095
        int r = idx >> 5, c2 = idx & 31;
        __half2 qv = *(const __half2*)(baseQ + (size_t)(t0 + r) * QKVN + c2 * 2);
        float2 qf = __half22float2(qv);
        Qs[r][c2 * 2] = qf.x; Qs[r][c2 * 2 + 1] = qf.y;
    }
    __syncthreads();

    int j = tid & 63, rb = tid >> 6;
    __half* outbase = cat + (size_t)(b * Tv + t0) * Cv + h * 64 + j;
    #pragma unroll
    for (int rr = 0; rr < 32; rr++) {
        int row = rb * 32 + rr;
        float acc = 0.f;
        #pragma unroll
        for (int i = 0; i < 64; i++) acc += Qs[row][i] * Ms[i][j];
        outbase[(size_t)row * Cv] = __float2half(acc);
    }
}

// ---------------- launch ----------------
extern "C" void kernel_launch(void* const* d_in, const int* in_sizes, int n_in,
                              void* d_out, int out_size)
{
    (void)in_sizes; (void)n_in; (void)out_size;
    const float* x    = (const float*)d_in[0];
    const float* Wq   = (const float*)d_in[1];
    const float* bq   = (const float*)d_in[2];
    const float* Wk   = (const float*)d_in[3];
    const float* bk   = (const float*)d_in[4];
    const float* Wv   = (const float*)d_in[5];
    const float* bv   = (const float*)d_in[6];
    const float* Wp   = (const float*)d_in[7];
    const float* bp   = (const float*)d_in[8];
    const float* W1   = (const float*)d_in[9];
    const float* b1   = (const float*)d_in[10];
    const float* W2   = (const float*)d_in[11];
    const float* b2   = (const float*)d_in[12];
    const float* ln1w = (const float*)d_in[13];
    const float* ln1b = (const float*)d_in[14];
    const float* ln2w = (const float*)d_in[15];
    const float* ln2b = (const float*)d_in[16];
    float* out = (float*)d_out;

    float *px1, *pbqkv, *pMp, *py, *px2;
    __half *px1h, *pqkvh, *pWqkvh, *pcath, *px2h, *phh, *pWpTh, *pW1Th, *pW2Th;
    cudaGetSymbolAddress((void**)&px1,    g_x1);
    cudaGetSymbolAddress((void**)&px1h,   g_x1h);
    cudaGetSymbolAddress((void**)&pqkvh,  g_qkvh);
    cudaGetSymbolAddress((void**)&pWqkvh, g_Wqkvh);
    cudaGetSymbolAddress((void**)&pbqkv,  g_bqkv);
    cudaGetSymbolAddress((void**)&pMp,    g_Mpart);
    cudaGetSymbolAddress((void**)&pcath,  g_cath);
    cudaGetSymbolAddress((void**)&py,     g_y);
    cudaGetSymbolAddress((void**)&px2,    g_x2);
    cudaGetSymbolAddress((void**)&px2h,   g_x2h);
    cudaGetSymbolAddress((void**)&phh,    g_hh);
    cudaGetSymbolAddress((void**)&pWpTh,  g_WpTh);
    cudaGetSymbolAddress((void**)&pW1Th,  g_W1Th);
    cudaGetSymbolAddress((void**)&pW2Th,  g_W2Th);

    const int smem = NSTAGE * STAGEB;   // 73728
    cudaFuncSetAttribute(mm_gemm<0,1>, cudaFuncAttributeMaxDynamicSharedMemorySize, smem);
    cudaFuncSetAttribute(mm_gemm<1,0>, cudaFuncAttributeMaxDynamicSharedMemorySize, smem);
    cudaFuncSetAttribute(mm_gemm<2,1>, cudaFuncAttributeMaxDynamicSharedMemorySize, smem);

    // weight prep (fp16, [N,K] layouts)
    pack_kernel<<<(QKVN * Cv + 255) / 256, 256>>>(Wq, Wk, Wv, bq, bk, bv, pWqkvh, pbqkv);
    transpose_kernel<<<dim3(Cv/32, Cv/32), dim3(32,8)>>>(Wp, pWpTh, Cv, Cv);
    transpose_kernel<<<dim3(Fv/32, Cv/32), dim3(32,8)>>>(W1, pW1Th, Cv, Fv);
    transpose_kernel<<<dim3(Cv/32, Fv/32), dim3(32,8)>>>(W2, pW2Th, Fv, Cv);

    // x1 = LN1(x) (fp32 + fp16)
    ln_kernel<<<BT, 256>>>(x, ln1w, ln1b, px1, px1h);
    // qkv = x1 @ Wqkv^T + b   -> fp16
    mm_gemm<0,1><<<dim3(QKVN/128, BT/128), 256, smem>>>(px1h, pWqkvh, pbqkv, nullptr, pqkvh, BT, QKVN, Cv);
    // attention collapsed (4-way T split + qm-side reduce), fp16 inputs
    ktv_kernel<<<dim3(Bv * Hv, 4), 256>>>(pqkvh, pMp);
    qm_kernel<<<dim3(Tv/128, Bv * Hv), 256>>>(pqkvh, pMp, pcath);
    // y = x1 + cat @ Wp + bp   -> fp32
    mm_gemm<1,0><<<dim3(Cv/128, BT/128), 256, smem>>>(pcath, pWpTh, bp, px1, py, BT, Cv, Cv);
    // x2 = LN2(y) (fp32 + fp16)
    ln_kernel<<<BT, 256>>>(py, ln2w, ln2b, px2, px2h);
    // h = gelu(x2 @ W1 + b1)   -> fp16
    mm_gemm<2,1><<<dim3(Fv/128, BT/128), 256, smem>>>(px2h, pW1Th, b1, nullptr, phh, BT, Fv, Cv);
    // out = x2 + h @ W2 + b2   -> fp32
    mm_gemm<1,0><<<dim3(Cv/128, BT/128), 256, smem>>>(phh, pW2Th, b2, px2, out, BT, Cv, Fv);
}